// round 9
// baseline (speedup 1.0000x reference)
#include <cuda_runtime.h>
#include <cuda_fp16.h>
#include <math.h>
#include <stdint.h>

#define M_TOT 12608
#define D_DIM 768
#define H_DIM 3072
#define R_DIM 16

#define BM 128
#define BK 64
#define STAGES 3
#define ROWSTRIDE 72   // 64 fp16 + 8 pad

// ---------------------------------------------------------------------------
// Device-global scratch (fp16 operands)
// ---------------------------------------------------------------------------
__device__ __align__(16) __half g_x_hi [(size_t)M_TOT * D_DIM];
__device__ __align__(16) __half g_x_lo [(size_t)M_TOT * D_DIM];
__device__ __align__(16) __half g_w1   [(size_t)H_DIM * D_DIM];
__device__ __align__(16) __half g_w2   [(size_t)D_DIM * H_DIM];
__device__ __align__(16) __half g_h_hi [(size_t)M_TOT * H_DIM];
__device__ __align__(16) __half g_h_lo [(size_t)M_TOT * H_DIM];
__device__ __align__(16) __half g_tc   [(size_t)M_TOT * 64];   // [Thi|Tlo|0|0]
__device__ __align__(16) __half g_bc1  [(size_t)H_DIM * 64];   // [Bhi|Bhi|0|0]
__device__ __align__(16) __half g_bc2  [(size_t)D_DIM * 64];

// ---------------------------------------------------------------------------
// PTX helpers
// ---------------------------------------------------------------------------
__device__ __forceinline__ uint32_t smem_u32(const void* p) {
    uint32_t a;
    asm("{ .reg .u64 t; cvta.to.shared.u64 t, %1; cvt.u32.u64 %0, t; }" : "=r"(a) : "l"(p));
    return a;
}
#define CP_ASYNC16(dst, src) \
    asm volatile("cp.async.cg.shared.global [%0], [%1], 16;" :: "r"(dst), "l"(src))
#define CP_COMMIT() asm volatile("cp.async.commit_group;" ::: "memory")
#define CP_WAIT(n)  asm volatile("cp.async.wait_group %0;" :: "n"(n) : "memory")

#define LDSM4(r, addr) \
    asm volatile("ldmatrix.sync.aligned.m8n8.x4.shared.b16 {%0,%1,%2,%3}, [%4];" \
                 : "=r"((r)[0]), "=r"((r)[1]), "=r"((r)[2]), "=r"((r)[3]) : "r"(addr))

#define MMA16816H(d, a, b0, b1) \
    asm volatile("mma.sync.aligned.m16n8k16.row.col.f32.f16.f16.f32 " \
                 "{%0,%1,%2,%3}, {%4,%5,%6,%7}, {%8,%9}, {%0,%1,%2,%3};" \
                 : "+f"((d)[0]), "+f"((d)[1]), "+f"((d)[2]), "+f"((d)[3]) \
                 : "r"((a)[0]), "r"((a)[1]), "r"((a)[2]), "r"((a)[3]), \
                   "r"(b0), "r"(b1))

__device__ __forceinline__ uint32_t pack2h(float a, float b) {
    __half2 h = __floats2half2_rn(a, b);
    return *(uint32_t*)&h;
}

__device__ __forceinline__ void split_store4h(const float4 v, uint2* dhi, uint2* dlo, int i) {
    __half hx = __float2half_rn(v.x), hy = __float2half_rn(v.y);
    __half hz = __float2half_rn(v.z), hw = __float2half_rn(v.w);
    uint2 uh, ul;
    __half2 p0 = __halves2half2(hx, hy), p1 = __halves2half2(hz, hw);
    uh.x = *(uint32_t*)&p0;
    uh.y = *(uint32_t*)&p1;
    ul.x = pack2h(v.x - __half2float(hx), v.y - __half2float(hy));
    ul.y = pack2h(v.z - __half2float(hz), v.w - __half2float(hw));
    dhi[i] = uh;
    dlo[i] = ul;
}

// ---------------------------------------------------------------------------
// prep_all: x split + W1/W2 fp16 + bc1/bc2 (single launch)
// ---------------------------------------------------------------------------
__global__ __launch_bounds__(256)
void prep_all_kernel(const float4* __restrict__ x, uint2* __restrict__ xhi, uint2* __restrict__ xlo,
                     const float4* __restrict__ W1, uint2* __restrict__ w1h,
                     const float4* __restrict__ W2, uint2* __restrict__ w2h,
                     const float* __restrict__ B1f, __half* __restrict__ bc1,
                     const float* __restrict__ B2f, __half* __restrict__ bc2) {
    const int stride = gridDim.x * blockDim.x;
    const int tid0 = blockIdx.x * blockDim.x + threadIdx.x;
    const int nx4 = M_TOT * D_DIM / 4;
    const int nw4 = H_DIM * D_DIM / 4;
    for (int i = tid0; i < nx4; i += stride) split_store4h(x[i], xhi, xlo, i);
    for (int i = tid0; i < nw4; i += stride) {
        float4 v = W1[i];
        uint2 u;
        u.x = pack2h(v.x, v.y);
        u.y = pack2h(v.z, v.w);
        w1h[i] = u;
    }
    for (int i = tid0; i < nw4; i += stride) {
        float4 v = W2[i];
        uint2 u;
        u.x = pack2h(v.x, v.y);
        u.y = pack2h(v.z, v.w);
        w2h[i] = u;
    }
    const __half hz = __float2half_rn(0.f);
    for (int n = tid0; n < H_DIM; n += stride) {
#pragma unroll
        for (int r = 0; r < 16; r++) {
            __half hi = __float2half_rn(B1f[n * 16 + r]);
            bc1[(size_t)n * 64 + r] = hi;
            bc1[(size_t)n * 64 + 16 + r] = hi;
            bc1[(size_t)n * 64 + 32 + r] = hz;
            bc1[(size_t)n * 64 + 48 + r] = hz;
        }
    }
    for (int n = tid0; n < D_DIM; n += stride) {
#pragma unroll
        for (int r = 0; r < 16; r++) {
            __half hi = __float2half_rn(B2f[n * 16 + r]);
            bc2[(size_t)n * 64 + r] = hi;
            bc2[(size_t)n * 64 + 16 + r] = hi;
            bc2[(size_t)n * 64 + 32 + r] = hz;
            bc2[(size_t)n * 64 + 48 + r] = hz;
        }
    }
}

// ---------------------------------------------------------------------------
// LoRA rank projections -> Tc row [Thi|Tlo|0|0] (64 wide)
// ---------------------------------------------------------------------------
__global__ __launch_bounds__(256)
void proj_f32_kernel(const float* __restrict__ X, const float* __restrict__ A,
                     __half* __restrict__ Tc, int Kd) {
    int row = blockIdx.x * 16 + threadIdx.y;
    int col = threadIdx.x;
    const float4* xr = (const float4*)(X + (size_t)row * Kd);
    const float4* ar = (const float4*)(A + (size_t)col * Kd);
    float acc = 0.f;
    int kv = Kd >> 2;
#pragma unroll 4
    for (int i = 0; i < kv; i++) {
        float4 a = xr[i], b = ar[i];
        acc += a.x * b.x + a.y * b.y + a.z * b.z + a.w * b.w;
    }
    __half hi = __float2half_rn(acc);
    __half lo = __float2half_rn(acc - __half2float(hi));
    const __half hz = __float2half_rn(0.f);
    Tc[(size_t)row * 64 + col] = hi;
    Tc[(size_t)row * 64 + 16 + col] = lo;
    Tc[(size_t)row * 64 + 32 + col] = hz;
    Tc[(size_t)row * 64 + 48 + col] = hz;
}

__global__ __launch_bounds__(256)
void proj_split_kernel(const __half* __restrict__ Hhi, const __half* __restrict__ Hlo,
                       const float* __restrict__ A, __half* __restrict__ Tc, int Kd) {
    int row = blockIdx.x * 16 + threadIdx.y;
    int col = threadIdx.x;
    const uint2* hh = (const uint2*)(Hhi + (size_t)row * Kd);
    const uint2* hl = (const uint2*)(Hlo + (size_t)row * Kd);
    const float4* ar = (const float4*)(A + (size_t)col * Kd);
    float acc = 0.f;
    int kv = Kd >> 2;
#pragma unroll 4
    for (int i = 0; i < kv; i++) {
        uint2 uh = hh[i], ul = hl[i];
        float4 a = ar[i];
        float2 h0 = __half22float2(*(__half2*)&uh.x);
        float2 h1 = __half22float2(*(__half2*)&uh.y);
        float2 l0 = __half22float2(*(__half2*)&ul.x);
        float2 l1 = __half22float2(*(__half2*)&ul.y);
        acc += (h0.x + l0.x) * a.x + (h0.y + l0.y) * a.y +
               (h1.x + l1.x) * a.z + (h1.y + l1.y) * a.w;
    }
    __half hi = __float2half_rn(acc);
    __half lo = __float2half_rn(acc - __half2float(hi));
    const __half hz = __float2half_rn(0.f);
    Tc[(size_t)row * 64 + col] = hi;
    Tc[(size_t)row * 64 + 16 + col] = lo;
    Tc[(size_t)row * 64 + 32 + col] = hz;
    Tc[(size_t)row * 64 + 48 + col] = hz;
}

// ---------------------------------------------------------------------------
// K-dim segments (2 split passes + LoRA tail), BK=64 chunks
// ---------------------------------------------------------------------------
struct Segs {
    const __half* a[3];
    const __half* b[3];
    int sa[3];
    int sb[3];
    int nchunks[3];
};

// ---------------------------------------------------------------------------
// fp16 mma.sync GEMM. CTA 128 x BNT, BK=64/iter (2 sub-chunks), 256 threads,
// 8 warps (warp tile 32 x BNT/2), 2 CTAs/SM, 1 barrier per BK=64.
// ---------------------------------------------------------------------------
template <int DO_GELU, int BNT>
__global__ __launch_bounds__(256, 2)
void fc_mma_kernel(Segs segs, int total_chunks,
                   const float* __restrict__ bias,
                   __half* __restrict__ Chi, __half* __restrict__ Clo,
                   float* __restrict__ Cf, int Nld) {
    constexpr int NJ = BNT / 32;                 // 16-col groups per warp
    constexpr int A_BYTES = BM * ROWSTRIDE * 2;  // 18432
    constexpr int B_BYTES = BNT * ROWSTRIDE * 2;
    constexpr int STG_BYTES = A_BYTES + B_BYTES;

    extern __shared__ char smem[];
    const uint32_t smem_base = smem_u32(smem);

    const int tid = threadIdx.x;
    const int wid = tid >> 5;
    const int lane = tid & 31;
    const int wm = wid >> 1;
    const int wn = wid & 1;
    const int m0 = blockIdx.y * BM;
    const int n0 = blockIdx.x * BNT;

    int ls = 0, lc = 0;

    const uint32_t aoff = ((uint32_t)(wm * 32 + (lane & 15)) * ROWSTRIDE + (lane >> 4) * 8) * 2;
    const uint32_t boff = ((uint32_t)(wn * (BNT / 2) + ((lane >> 4) & 1) * 8 + (lane & 7)) * ROWSTRIDE +
                           ((lane >> 3) & 1) * 8) * 2;

    float acc[2][NJ * 2][4];
#pragma unroll
    for (int i = 0; i < 2; i++)
#pragma unroll
        for (int j = 0; j < NJ * 2; j++)
#pragma unroll
            for (int k = 0; k < 4; k++) acc[i][j][k] = 0.f;

    auto load_tile = [&](int stage) {
        const __half* Ap = segs.a[ls];
        const __half* Bp = segs.b[ls];
        const int stA = segs.sa[ls];
        const int stB = segs.sb[ls];
        const int kk = lc * BK;
        const uint32_t sA = smem_base + stage * STG_BYTES;
        const uint32_t sB = sA + A_BYTES;
        // A: 128 rows x 8 units = 1024 -> wait, 128 rows x (64/8)=8 units/row
        // = 1024 units? No: 64 halves = 128B = 8 16B-units per row -> 1024
        // units over 256 threads = 4 iters? That's 2x the old per-chunk load,
        // matching 2x K. u layout: row = u>>3, grp = u&7.
#pragma unroll
        for (int j = 0; j < 4; j++) {
            int u = j * 256 + tid;
            int row = u >> 3, grp = u & 7;
            int gm = m0 + row;
            if (gm >= M_TOT) gm = M_TOT - 1;
            CP_ASYNC16(sA + (uint32_t)(row * ROWSTRIDE + grp * 8) * 2,
                       Ap + (size_t)gm * stA + kk + grp * 8);
        }
#pragma unroll
        for (int j = 0; j < BNT / 32; j++) {   // BNT rows x 8 units / 256 thr
            int u = j * 256 + tid;
            int row = u >> 3, grp = u & 7;
            CP_ASYNC16(sB + (uint32_t)(row * ROWSTRIDE + grp * 8) * 2,
                       Bp + (size_t)(n0 + row) * stB + kk + grp * 8);
        }
        if (++lc == segs.nchunks[ls]) { lc = 0; ++ls; }
    };

#pragma unroll
    for (int s = 0; s < STAGES - 1; s++) {
        load_tile(s);
        CP_COMMIT();
    }

    for (int t = 0; t < total_chunks; t++) {
        CP_WAIT(STAGES - 2);
        __syncthreads();

        const uint32_t sA = smem_base + (t % STAGES) * STG_BYTES;
        const uint32_t sB = sA + A_BYTES;

#pragma unroll
        for (int sub = 0; sub < 2; sub++) {
            const uint32_t ksub = (uint32_t)(sub * 32) * 2;  // byte offset of K-half
            uint32_t af[2][2][4];
#pragma unroll
            for (int mi = 0; mi < 2; mi++)
#pragma unroll
                for (int k = 0; k < 2; k++)
                    LDSM4(af[mi][k], sA + aoff + ksub + (uint32_t)(mi * 16 * ROWSTRIDE + k * 16) * 2);

#pragma unroll
            for (int nj = 0; nj < NJ; nj++) {
                uint32_t bf[2][4];
#pragma unroll
                for (int k = 0; k < 2; k++)
                    LDSM4(bf[k], sB + boff + ksub + (uint32_t)(nj * 16 * ROWSTRIDE + k * 16) * 2);
#pragma unroll
                for (int mi = 0; mi < 2; mi++)
#pragma unroll
                    for (int h = 0; h < 2; h++) {
                        MMA16816H(acc[mi][nj * 2 + h], af[mi][0], bf[0][h * 2], bf[0][h * 2 + 1]);
                        MMA16816H(acc[mi][nj * 2 + h], af[mi][1], bf[1][h * 2], bf[1][h * 2 + 1]);
                    }
            }
        }

        if (t + STAGES - 1 < total_chunks) load_tile((t + STAGES - 1) % STAGES);
        CP_COMMIT();
    }

    // ---- epilogue ----
#pragma unroll
    for (int mi = 0; mi < 2; mi++) {
        const int rbase = m0 + wm * 32 + mi * 16 + (lane >> 2);
#pragma unroll
        for (int ni = 0; ni < NJ * 2; ni++) {
            const int gn = n0 + wn * (BNT / 2) + ni * 8 + (lane & 3) * 2;
            const float b0 = __ldg(bias + gn);
            const float b1 = __ldg(bias + gn + 1);
#pragma unroll
            for (int h = 0; h < 2; h++) {
                const int gm = rbase + h * 8;
                if (gm >= M_TOT) continue;
                float v0 = acc[mi][ni][h * 2 + 0] + b0;
                float v1 = acc[mi][ni][h * 2 + 1] + b1;
                if (DO_GELU) {
                    v0 = 0.5f * v0 * (1.0f + erff(v0 * 0.70710678118654752f));
                    v1 = 0.5f * v1 * (1.0f + erff(v1 * 0.70710678118654752f));
                    __half h0 = __float2half_rn(v0);
                    __half h1 = __float2half_rn(v1);
                    __half2 ph = __halves2half2(h0, h1);
                    *(uint32_t*)(Chi + (size_t)gm * Nld + gn) = *(uint32_t*)&ph;
                    *(uint32_t*)(Clo + (size_t)gm * Nld + gn) =
                        pack2h(v0 - __half2float(h0), v1 - __half2float(h1));
                } else {
                    *(float2*)(Cf + (size_t)gm * Nld + gn) = make_float2(v0, v1);
                }
            }
        }
    }
}

// ---------------------------------------------------------------------------
// Launch sequence: prep_all, proj_f32, fc1(128x128), proj_split, fc2(128x64)
// ---------------------------------------------------------------------------
extern "C" void kernel_launch(void* const* d_in, const int* in_sizes, int n_in,
                              void* d_out, int out_size) {
    const float* x  = (const float*)d_in[0];
    const float* W1 = (const float*)d_in[1];
    const float* b1 = (const float*)d_in[2];
    const float* A1 = (const float*)d_in[3];
    const float* B1 = (const float*)d_in[4];
    const float* W2 = (const float*)d_in[5];
    const float* b2 = (const float*)d_in[6];
    const float* A2 = (const float*)d_in[7];
    const float* B2 = (const float*)d_in[8];
    float* out = (float*)d_out;

    __half *xhi, *xlo, *w1h, *w2h, *hhi, *hlo, *tc, *bc1, *bc2;
    cudaGetSymbolAddress((void**)&xhi, g_x_hi);
    cudaGetSymbolAddress((void**)&xlo, g_x_lo);
    cudaGetSymbolAddress((void**)&w1h, g_w1);
    cudaGetSymbolAddress((void**)&w2h, g_w2);
    cudaGetSymbolAddress((void**)&hhi, g_h_hi);
    cudaGetSymbolAddress((void**)&hlo, g_h_lo);
    cudaGetSymbolAddress((void**)&tc,  g_tc);
    cudaGetSymbolAddress((void**)&bc1, g_bc1);
    cudaGetSymbolAddress((void**)&bc2, g_bc2);

    constexpr int SM1 = STAGES * (BM * ROWSTRIDE * 2 + 128 * ROWSTRIDE * 2);  // fc1: 110592
    constexpr int SM2 = STAGES * (BM * ROWSTRIDE * 2 + 64 * ROWSTRIDE * 2);   // fc2: 82944
    cudaFuncSetAttribute((const void*)fc_mma_kernel<1, 128>,
                         cudaFuncAttributeMaxDynamicSharedMemorySize, SM1);
    cudaFuncSetAttribute((const void*)fc_mma_kernel<0, 64>,
                         cudaFuncAttributeMaxDynamicSharedMemorySize, SM2);

    prep_all_kernel<<<592, 256>>>(
        (const float4*)x, (uint2*)xhi, (uint2*)xlo,
        (const float4*)W1, (uint2*)w1h,
        (const float4*)W2, (uint2*)w2h,
        B1, bc1, B2, bc2);

    dim3 blkP(16, 16);
    proj_f32_kernel<<<M_TOT / 16, blkP>>>(x, A1, tc, D_DIM);

    {
        Segs s;
        s.a[0] = xhi; s.b[0] = w1h; s.sa[0] = D_DIM; s.sb[0] = D_DIM; s.nchunks[0] = D_DIM / BK;
        s.a[1] = xlo; s.b[1] = w1h; s.sa[1] = D_DIM; s.sb[1] = D_DIM; s.nchunks[1] = D_DIM / BK;
        s.a[2] = tc;  s.b[2] = bc1; s.sa[2] = 64;    s.sb[2] = 64;    s.nchunks[2] = 1;
        int total = 2 * (D_DIM / BK) + 1;  // 25
        dim3 grid(H_DIM / 128, (M_TOT + BM - 1) / BM);
        fc_mma_kernel<1, 128><<<grid, 256, SM1>>>(s, total, b1, hhi, hlo, nullptr, H_DIM);
    }

    proj_split_kernel<<<M_TOT / 16, blkP>>>(hhi, hlo, A2, tc, H_DIM);

    {
        Segs s;
        s.a[0] = hhi; s.b[0] = w2h; s.sa[0] = H_DIM; s.sb[0] = H_DIM; s.nchunks[0] = H_DIM / BK;
        s.a[1] = hlo; s.b[1] = w2h; s.sa[1] = H_DIM; s.sb[1] = H_DIM; s.nchunks[1] = H_DIM / BK;
        s.a[2] = tc;  s.b[2] = bc2; s.sa[2] = 64;    s.sb[2] = 64;    s.nchunks[2] = 1;
        int total = 2 * (H_DIM / BK) + 1;  // 97
        dim3 grid(D_DIM / 64, (M_TOT + BM - 1) / BM);
        fc_mma_kernel<0, 64><<<grid, 256, SM2>>>(s, total, b2, nullptr, nullptr, out, D_DIM);
    }
}

// round 10
// speedup vs baseline: 1.0640x; 1.0640x over previous
#include <cuda_runtime.h>
#include <cuda_fp16.h>
#include <math.h>
#include <stdint.h>

#define M_TOT 12608
#define D_DIM 768
#define H_DIM 3072
#define R_DIM 16

#define BM 128
#define BK 64
#define STAGES 3
#define ROWSTRIDE 72   // 64 fp16 + 8 pad

// ---------------------------------------------------------------------------
// Device-global scratch (fp16 operands)
// ---------------------------------------------------------------------------
__device__ __align__(16) __half g_x_hi [(size_t)M_TOT * D_DIM];
__device__ __align__(16) __half g_x_lo [(size_t)M_TOT * D_DIM];
__device__ __align__(16) __half g_w1   [(size_t)H_DIM * D_DIM];
__device__ __align__(16) __half g_w2   [(size_t)D_DIM * H_DIM];
__device__ __align__(16) __half g_h_hi [(size_t)M_TOT * H_DIM];
__device__ __align__(16) __half g_h_lo [(size_t)M_TOT * H_DIM];
__device__ __align__(16) __half g_tc   [(size_t)M_TOT * 64];   // [Thi|Tlo|0|0]
__device__ __align__(16) __half g_bc1  [(size_t)H_DIM * 64];   // [Bhi|Bhi|0|0]
__device__ __align__(16) __half g_bc2  [(size_t)D_DIM * 64];

// ---------------------------------------------------------------------------
// PTX helpers
// ---------------------------------------------------------------------------
__device__ __forceinline__ uint32_t smem_u32(const void* p) {
    uint32_t a;
    asm("{ .reg .u64 t; cvta.to.shared.u64 t, %1; cvt.u32.u64 %0, t; }" : "=r"(a) : "l"(p));
    return a;
}
#define CP_ASYNC16(dst, src) \
    asm volatile("cp.async.cg.shared.global [%0], [%1], 16;" :: "r"(dst), "l"(src))
#define CP_COMMIT() asm volatile("cp.async.commit_group;" ::: "memory")
#define CP_WAIT(n)  asm volatile("cp.async.wait_group %0;" :: "n"(n) : "memory")

#define LDSM4(r, addr) \
    asm volatile("ldmatrix.sync.aligned.m8n8.x4.shared.b16 {%0,%1,%2,%3}, [%4];" \
                 : "=r"((r)[0]), "=r"((r)[1]), "=r"((r)[2]), "=r"((r)[3]) : "r"(addr))

#define MMA16816H(d, a, b0, b1) \
    asm volatile("mma.sync.aligned.m16n8k16.row.col.f32.f16.f16.f32 " \
                 "{%0,%1,%2,%3}, {%4,%5,%6,%7}, {%8,%9}, {%0,%1,%2,%3};" \
                 : "+f"((d)[0]), "+f"((d)[1]), "+f"((d)[2]), "+f"((d)[3]) \
                 : "r"((a)[0]), "r"((a)[1]), "r"((a)[2]), "r"((a)[3]), \
                   "r"(b0), "r"(b1))

__device__ __forceinline__ uint32_t pack2h(float a, float b) {
    __half2 h = __floats2half2_rn(a, b);
    return *(uint32_t*)&h;
}

__device__ __forceinline__ void split_store4h(const float4 v, uint2* dhi, uint2* dlo, int i) {
    __half hx = __float2half_rn(v.x), hy = __float2half_rn(v.y);
    __half hz = __float2half_rn(v.z), hw = __float2half_rn(v.w);
    uint2 uh, ul;
    __half2 p0 = __halves2half2(hx, hy), p1 = __halves2half2(hz, hw);
    uh.x = *(uint32_t*)&p0;
    uh.y = *(uint32_t*)&p1;
    ul.x = pack2h(v.x - __half2float(hx), v.y - __half2float(hy));
    ul.y = pack2h(v.z - __half2float(hz), v.w - __half2float(hw));
    dhi[i] = uh;
    dlo[i] = ul;
}

// ---------------------------------------------------------------------------
// prep_all: x split + W1/W2 fp16 + bc1/bc2 (single launch)
// ---------------------------------------------------------------------------
__global__ __launch_bounds__(256)
void prep_all_kernel(const float4* __restrict__ x, uint2* __restrict__ xhi, uint2* __restrict__ xlo,
                     const float4* __restrict__ W1, uint2* __restrict__ w1h,
                     const float4* __restrict__ W2, uint2* __restrict__ w2h,
                     const float* __restrict__ B1f, __half* __restrict__ bc1,
                     const float* __restrict__ B2f, __half* __restrict__ bc2) {
    const int stride = gridDim.x * blockDim.x;
    const int tid0 = blockIdx.x * blockDim.x + threadIdx.x;
    const int nx4 = M_TOT * D_DIM / 4;
    const int nw4 = H_DIM * D_DIM / 4;
    for (int i = tid0; i < nx4; i += stride) split_store4h(x[i], xhi, xlo, i);
    for (int i = tid0; i < nw4; i += stride) {
        float4 v = W1[i];
        uint2 u;
        u.x = pack2h(v.x, v.y);
        u.y = pack2h(v.z, v.w);
        w1h[i] = u;
    }
    for (int i = tid0; i < nw4; i += stride) {
        float4 v = W2[i];
        uint2 u;
        u.x = pack2h(v.x, v.y);
        u.y = pack2h(v.z, v.w);
        w2h[i] = u;
    }
    const __half hz = __float2half_rn(0.f);
    for (int n = tid0; n < H_DIM; n += stride) {
#pragma unroll
        for (int r = 0; r < 16; r++) {
            __half hi = __float2half_rn(B1f[n * 16 + r]);
            bc1[(size_t)n * 64 + r] = hi;
            bc1[(size_t)n * 64 + 16 + r] = hi;
            bc1[(size_t)n * 64 + 32 + r] = hz;
            bc1[(size_t)n * 64 + 48 + r] = hz;
        }
    }
    for (int n = tid0; n < D_DIM; n += stride) {
#pragma unroll
        for (int r = 0; r < 16; r++) {
            __half hi = __float2half_rn(B2f[n * 16 + r]);
            bc2[(size_t)n * 64 + r] = hi;
            bc2[(size_t)n * 64 + 16 + r] = hi;
            bc2[(size_t)n * 64 + 32 + r] = hz;
            bc2[(size_t)n * 64 + 48 + r] = hz;
        }
    }
}

// ---------------------------------------------------------------------------
// proj_f32: t = X(fp32) @ A^T -> Tc row [Thi|Tlo|0|0]
// block 16x8 (col x row), 4 independent acc chains, 16 floats/iter
// ---------------------------------------------------------------------------
__global__ __launch_bounds__(128)
void proj_f32_kernel(const float* __restrict__ X, const float* __restrict__ A,
                     __half* __restrict__ Tc, int Kd) {
    int row = blockIdx.x * 8 + threadIdx.y;
    int col = threadIdx.x;
    const float4* xr = (const float4*)(X + (size_t)row * Kd);
    const float4* ar = (const float4*)(A + (size_t)col * Kd);
    float a0 = 0.f, a1 = 0.f, a2 = 0.f, a3 = 0.f;
    const int it = Kd >> 4;   // 16 floats per iteration
    for (int i = 0; i < it; i++) {
        float4 x0 = xr[i * 4 + 0], x1 = xr[i * 4 + 1];
        float4 x2 = xr[i * 4 + 2], x3 = xr[i * 4 + 3];
        float4 q0 = ar[i * 4 + 0], q1 = ar[i * 4 + 1];
        float4 q2 = ar[i * 4 + 2], q3 = ar[i * 4 + 3];
        a0 += x0.x * q0.x + x0.y * q0.y + x0.z * q0.z + x0.w * q0.w;
        a1 += x1.x * q1.x + x1.y * q1.y + x1.z * q1.z + x1.w * q1.w;
        a2 += x2.x * q2.x + x2.y * q2.y + x2.z * q2.z + x2.w * q2.w;
        a3 += x3.x * q3.x + x3.y * q3.y + x3.z * q3.z + x3.w * q3.w;
    }
    float acc = (a0 + a1) + (a2 + a3);
    __half hi = __float2half_rn(acc);
    __half lo = __float2half_rn(acc - __half2float(hi));
    const __half hz = __float2half_rn(0.f);
    Tc[(size_t)row * 64 + col] = hi;
    Tc[(size_t)row * 64 + 16 + col] = lo;
    Tc[(size_t)row * 64 + 32 + col] = hz;
    Tc[(size_t)row * 64 + 48 + col] = hz;
}

// ---------------------------------------------------------------------------
// proj_split: t = Hhi(fp16) @ A^T (lo residual of h dropped -- its
// contribution to out via B2 (~0.01 scale) is ~1e-6 relative).
// block 16x8, 4 acc chains, 16 halves/iter
// ---------------------------------------------------------------------------
__global__ __launch_bounds__(128)
void proj_split_kernel(const __half* __restrict__ Hhi,
                       const float* __restrict__ A, __half* __restrict__ Tc, int Kd) {
    int row = blockIdx.x * 8 + threadIdx.y;
    int col = threadIdx.x;
    const uint2* hh = (const uint2*)(Hhi + (size_t)row * Kd);
    const float4* ar = (const float4*)(A + (size_t)col * Kd);
    float a0 = 0.f, a1 = 0.f, a2 = 0.f, a3 = 0.f;
    const int it = Kd >> 4;   // 16 halves per iteration (4 uint2)
    for (int i = 0; i < it; i++) {
        uint2 u0 = hh[i * 4 + 0], u1 = hh[i * 4 + 1];
        uint2 u2 = hh[i * 4 + 2], u3 = hh[i * 4 + 3];
        float4 q0 = ar[i * 4 + 0], q1 = ar[i * 4 + 1];
        float4 q2 = ar[i * 4 + 2], q3 = ar[i * 4 + 3];
        float2 h00 = __half22float2(*(__half2*)&u0.x), h01 = __half22float2(*(__half2*)&u0.y);
        float2 h10 = __half22float2(*(__half2*)&u1.x), h11 = __half22float2(*(__half2*)&u1.y);
        float2 h20 = __half22float2(*(__half2*)&u2.x), h21 = __half22float2(*(__half2*)&u2.y);
        float2 h30 = __half22float2(*(__half2*)&u3.x), h31 = __half22float2(*(__half2*)&u3.y);
        a0 += h00.x * q0.x + h00.y * q0.y + h01.x * q0.z + h01.y * q0.w;
        a1 += h10.x * q1.x + h10.y * q1.y + h11.x * q1.z + h11.y * q1.w;
        a2 += h20.x * q2.x + h20.y * q2.y + h21.x * q2.z + h21.y * q2.w;
        a3 += h30.x * q3.x + h30.y * q3.y + h31.x * q3.z + h31.y * q3.w;
    }
    float acc = (a0 + a1) + (a2 + a3);
    __half hi = __float2half_rn(acc);
    __half lo = __float2half_rn(acc - __half2float(hi));
    const __half hz = __float2half_rn(0.f);
    Tc[(size_t)row * 64 + col] = hi;
    Tc[(size_t)row * 64 + 16 + col] = lo;
    Tc[(size_t)row * 64 + 32 + col] = hz;
    Tc[(size_t)row * 64 + 48 + col] = hz;
}

// ---------------------------------------------------------------------------
// K-dim segments (2 split passes + LoRA tail), BK=64 chunks
// ---------------------------------------------------------------------------
struct Segs {
    const __half* a[3];
    const __half* b[3];
    int sa[3];
    int sb[3];
    int nchunks[3];
};

// ---------------------------------------------------------------------------
// fp16 mma.sync GEMM. CTA 128 x BNT, BK=64/iter, 256 threads, 8 warps
// (warp tile 32 x BNT/2), 2 CTAs/SM, 1 barrier per BK=64.
// ---------------------------------------------------------------------------
template <int DO_GELU, int BNT>
__global__ __launch_bounds__(256, 2)
void fc_mma_kernel(Segs segs, int total_chunks,
                   const float* __restrict__ bias,
                   __half* __restrict__ Chi, __half* __restrict__ Clo,
                   float* __restrict__ Cf, int Nld) {
    constexpr int NJ = BNT / 32;
    constexpr int A_BYTES = BM * ROWSTRIDE * 2;
    constexpr int B_BYTES = BNT * ROWSTRIDE * 2;
    constexpr int STG_BYTES = A_BYTES + B_BYTES;

    extern __shared__ char smem[];
    const uint32_t smem_base = smem_u32(smem);

    const int tid = threadIdx.x;
    const int wid = tid >> 5;
    const int lane = tid & 31;
    const int wm = wid >> 1;
    const int wn = wid & 1;
    const int m0 = blockIdx.y * BM;
    const int n0 = blockIdx.x * BNT;

    int ls = 0, lc = 0;

    const uint32_t aoff = ((uint32_t)(wm * 32 + (lane & 15)) * ROWSTRIDE + (lane >> 4) * 8) * 2;
    const uint32_t boff = ((uint32_t)(wn * (BNT / 2) + ((lane >> 4) & 1) * 8 + (lane & 7)) * ROWSTRIDE +
                           ((lane >> 3) & 1) * 8) * 2;

    float acc[2][NJ * 2][4];
#pragma unroll
    for (int i = 0; i < 2; i++)
#pragma unroll
        for (int j = 0; j < NJ * 2; j++)
#pragma unroll
            for (int k = 0; k < 4; k++) acc[i][j][k] = 0.f;

    auto load_tile = [&](int stage) {
        const __half* Ap = segs.a[ls];
        const __half* Bp = segs.b[ls];
        const int stA = segs.sa[ls];
        const int stB = segs.sb[ls];
        const int kk = lc * BK;
        const uint32_t sA = smem_base + stage * STG_BYTES;
        const uint32_t sB = sA + A_BYTES;
#pragma unroll
        for (int j = 0; j < 4; j++) {
            int u = j * 256 + tid;
            int row = u >> 3, grp = u & 7;
            int gm = m0 + row;
            if (gm >= M_TOT) gm = M_TOT - 1;
            CP_ASYNC16(sA + (uint32_t)(row * ROWSTRIDE + grp * 8) * 2,
                       Ap + (size_t)gm * stA + kk + grp * 8);
        }
#pragma unroll
        for (int j = 0; j < BNT / 32; j++) {
            int u = j * 256 + tid;
            int row = u >> 3, grp = u & 7;
            CP_ASYNC16(sB + (uint32_t)(row * ROWSTRIDE + grp * 8) * 2,
                       Bp + (size_t)(n0 + row) * stB + kk + grp * 8);
        }
        if (++lc == segs.nchunks[ls]) { lc = 0; ++ls; }
    };

#pragma unroll
    for (int s = 0; s < STAGES - 1; s++) {
        load_tile(s);
        CP_COMMIT();
    }

    for (int t = 0; t < total_chunks; t++) {
        CP_WAIT(STAGES - 2);
        __syncthreads();

        const uint32_t sA = smem_base + (t % STAGES) * STG_BYTES;
        const uint32_t sB = sA + A_BYTES;

#pragma unroll
        for (int sub = 0; sub < 2; sub++) {
            const uint32_t ksub = (uint32_t)(sub * 32) * 2;
            uint32_t af[2][2][4];
#pragma unroll
            for (int mi = 0; mi < 2; mi++)
#pragma unroll
                for (int k = 0; k < 2; k++)
                    LDSM4(af[mi][k], sA + aoff + ksub + (uint32_t)(mi * 16 * ROWSTRIDE + k * 16) * 2);

#pragma unroll
            for (int nj = 0; nj < NJ; nj++) {
                uint32_t bf[2][4];
#pragma unroll
                for (int k = 0; k < 2; k++)
                    LDSM4(bf[k], sB + boff + ksub + (uint32_t)(nj * 16 * ROWSTRIDE + k * 16) * 2);
#pragma unroll
                for (int mi = 0; mi < 2; mi++)
#pragma unroll
                    for (int h = 0; h < 2; h++) {
                        MMA16816H(acc[mi][nj * 2 + h], af[mi][0], bf[0][h * 2], bf[0][h * 2 + 1]);
                        MMA16816H(acc[mi][nj * 2 + h], af[mi][1], bf[1][h * 2], bf[1][h * 2 + 1]);
                    }
            }
        }

        if (t + STAGES - 1 < total_chunks) load_tile((t + STAGES - 1) % STAGES);
        CP_COMMIT();
    }

    // ---- epilogue ----
#pragma unroll
    for (int mi = 0; mi < 2; mi++) {
        const int rbase = m0 + wm * 32 + mi * 16 + (lane >> 2);
#pragma unroll
        for (int ni = 0; ni < NJ * 2; ni++) {
            const int gn = n0 + wn * (BNT / 2) + ni * 8 + (lane & 3) * 2;
            const float b0 = __ldg(bias + gn);
            const float b1 = __ldg(bias + gn + 1);
#pragma unroll
            for (int h = 0; h < 2; h++) {
                const int gm = rbase + h * 8;
                if (gm >= M_TOT) continue;
                float v0 = acc[mi][ni][h * 2 + 0] + b0;
                float v1 = acc[mi][ni][h * 2 + 1] + b1;
                if (DO_GELU) {
                    v0 = 0.5f * v0 * (1.0f + erff(v0 * 0.70710678118654752f));
                    v1 = 0.5f * v1 * (1.0f + erff(v1 * 0.70710678118654752f));
                    __half h0 = __float2half_rn(v0);
                    __half h1 = __float2half_rn(v1);
                    __half2 ph = __halves2half2(h0, h1);
                    *(uint32_t*)(Chi + (size_t)gm * Nld + gn) = *(uint32_t*)&ph;
                    *(uint32_t*)(Clo + (size_t)gm * Nld + gn) =
                        pack2h(v0 - __half2float(h0), v1 - __half2float(h1));
                } else {
                    *(float2*)(Cf + (size_t)gm * Nld + gn) = make_float2(v0, v1);
                }
            }
        }
    }
}

// ---------------------------------------------------------------------------
// Launch sequence: prep_all, proj_f32, fc1(128x128), proj_split, fc2(128x64)
// ---------------------------------------------------------------------------
extern "C" void kernel_launch(void* const* d_in, const int* in_sizes, int n_in,
                              void* d_out, int out_size) {
    const float* x  = (const float*)d_in[0];
    const float* W1 = (const float*)d_in[1];
    const float* b1 = (const float*)d_in[2];
    const float* A1 = (const float*)d_in[3];
    const float* B1 = (const float*)d_in[4];
    const float* W2 = (const float*)d_in[5];
    const float* b2 = (const float*)d_in[6];
    const float* A2 = (const float*)d_in[7];
    const float* B2 = (const float*)d_in[8];
    float* out = (float*)d_out;

    __half *xhi, *xlo, *w1h, *w2h, *hhi, *hlo, *tc, *bc1, *bc2;
    cudaGetSymbolAddress((void**)&xhi, g_x_hi);
    cudaGetSymbolAddress((void**)&xlo, g_x_lo);
    cudaGetSymbolAddress((void**)&w1h, g_w1);
    cudaGetSymbolAddress((void**)&w2h, g_w2);
    cudaGetSymbolAddress((void**)&hhi, g_h_hi);
    cudaGetSymbolAddress((void**)&hlo, g_h_lo);
    cudaGetSymbolAddress((void**)&tc,  g_tc);
    cudaGetSymbolAddress((void**)&bc1, g_bc1);
    cudaGetSymbolAddress((void**)&bc2, g_bc2);

    constexpr int SM1 = STAGES * (BM * ROWSTRIDE * 2 + 128 * ROWSTRIDE * 2);
    constexpr int SM2 = STAGES * (BM * ROWSTRIDE * 2 + 64 * ROWSTRIDE * 2);
    cudaFuncSetAttribute((const void*)fc_mma_kernel<1, 128>,
                         cudaFuncAttributeMaxDynamicSharedMemorySize, SM1);
    cudaFuncSetAttribute((const void*)fc_mma_kernel<0, 64>,
                         cudaFuncAttributeMaxDynamicSharedMemorySize, SM2);

    prep_all_kernel<<<592, 256>>>(
        (const float4*)x, (uint2*)xhi, (uint2*)xlo,
        (const float4*)W1, (uint2*)w1h,
        (const float4*)W2, (uint2*)w2h,
        B1, bc1, B2, bc2);

    dim3 blkP(16, 8);
    proj_f32_kernel<<<M_TOT / 8, blkP>>>(x, A1, tc, D_DIM);

    {
        Segs s;
        s.a[0] = xhi; s.b[0] = w1h; s.sa[0] = D_DIM; s.sb[0] = D_DIM; s.nchunks[0] = D_DIM / BK;
        s.a[1] = xlo; s.b[1] = w1h; s.sa[1] = D_DIM; s.sb[1] = D_DIM; s.nchunks[1] = D_DIM / BK;
        s.a[2] = tc;  s.b[2] = bc1; s.sa[2] = 64;    s.sb[2] = 64;    s.nchunks[2] = 1;
        int total = 2 * (D_DIM / BK) + 1;  // 25
        dim3 grid(H_DIM / 128, (M_TOT + BM - 1) / BM);
        fc_mma_kernel<1, 128><<<grid, 256, SM1>>>(s, total, b1, hhi, hlo, nullptr, H_DIM);
    }

    proj_split_kernel<<<M_TOT / 8, blkP>>>(hhi, A2, tc, H_DIM);

    {
        Segs s;
        s.a[0] = hhi; s.b[0] = w2h; s.sa[0] = H_DIM; s.sb[0] = H_DIM; s.nchunks[0] = H_DIM / BK;
        s.a[1] = hlo; s.b[1] = w2h; s.sa[1] = H_DIM; s.sb[1] = H_DIM; s.nchunks[1] = H_DIM / BK;
        s.a[2] = tc;  s.b[2] = bc2; s.sa[2] = 64;    s.sb[2] = 64;    s.nchunks[2] = 1;
        int total = 2 * (H_DIM / BK) + 1;  // 97
        dim3 grid(D_DIM / 64, (M_TOT + BM - 1) / BM);
        fc_mma_kernel<0, 64><<<grid, 256, SM2>>>(s, total, b2, nullptr, nullptr, out, D_DIM);
    }
}

// round 11
// speedup vs baseline: 1.5309x; 1.4388x over previous
#include <cuda_runtime.h>
#include <cuda_fp16.h>
#include <math.h>
#include <stdint.h>

#define M_TOT 12608
#define D_DIM 768
#define H_DIM 3072
#define R_DIM 16

#define BM 128
#define BK 64
#define STAGES 3
#define ROWSTRIDE 72   // 64 fp16 + 8 pad

// ---------------------------------------------------------------------------
// Device-global scratch (fp16 operands)
// ---------------------------------------------------------------------------
__device__ __align__(16) __half g_x_hi [(size_t)M_TOT * D_DIM];
__device__ __align__(16) __half g_x_lo [(size_t)M_TOT * D_DIM];
__device__ __align__(16) __half g_w1   [(size_t)H_DIM * D_DIM];
__device__ __align__(16) __half g_w2   [(size_t)D_DIM * H_DIM];
__device__ __align__(16) __half g_h_hi [(size_t)M_TOT * H_DIM];
__device__ __align__(16) __half g_h_lo [(size_t)M_TOT * H_DIM];
__device__ __align__(16) __half g_tc   [(size_t)M_TOT * 64];   // [Thi|Tlo|0|0]
__device__ __align__(16) __half g_bc1  [(size_t)H_DIM * 64];   // [Bhi|Bhi|0|0]
__device__ __align__(16) __half g_bc2  [(size_t)D_DIM * 64];
__device__ __align__(16) __half g_at1  [(size_t)D_DIM * 16];   // A1^T [K][16] fp16
__device__ __align__(16) __half g_at2  [(size_t)H_DIM * 16];   // A2^T [K][16] fp16

// ---------------------------------------------------------------------------
// PTX helpers
// ---------------------------------------------------------------------------
__device__ __forceinline__ uint32_t smem_u32(const void* p) {
    uint32_t a;
    asm("{ .reg .u64 t; cvta.to.shared.u64 t, %1; cvt.u32.u64 %0, t; }" : "=r"(a) : "l"(p));
    return a;
}
#define CP_ASYNC16(dst, src) \
    asm volatile("cp.async.cg.shared.global [%0], [%1], 16;" :: "r"(dst), "l"(src))
#define CP_COMMIT() asm volatile("cp.async.commit_group;" ::: "memory")
#define CP_WAIT(n)  asm volatile("cp.async.wait_group %0;" :: "n"(n) : "memory")

#define LDSM4(r, addr) \
    asm volatile("ldmatrix.sync.aligned.m8n8.x4.shared.b16 {%0,%1,%2,%3}, [%4];" \
                 : "=r"((r)[0]), "=r"((r)[1]), "=r"((r)[2]), "=r"((r)[3]) : "r"(addr))

#define MMA16816H(d, a, b0, b1) \
    asm volatile("mma.sync.aligned.m16n8k16.row.col.f32.f16.f16.f32 " \
                 "{%0,%1,%2,%3}, {%4,%5,%6,%7}, {%8,%9}, {%0,%1,%2,%3};" \
                 : "+f"((d)[0]), "+f"((d)[1]), "+f"((d)[2]), "+f"((d)[3]) \
                 : "r"((a)[0]), "r"((a)[1]), "r"((a)[2]), "r"((a)[3]), \
                   "r"(b0), "r"(b1))

__device__ __forceinline__ uint32_t pack2h(float a, float b) {
    __half2 h = __floats2half2_rn(a, b);
    return *(uint32_t*)&h;
}

__device__ __forceinline__ void split_store4h(const float4 v, uint2* dhi, uint2* dlo, int i) {
    __half hx = __float2half_rn(v.x), hy = __float2half_rn(v.y);
    __half hz = __float2half_rn(v.z), hw = __float2half_rn(v.w);
    uint2 uh, ul;
    __half2 p0 = __halves2half2(hx, hy), p1 = __halves2half2(hz, hw);
    uh.x = *(uint32_t*)&p0;
    uh.y = *(uint32_t*)&p1;
    ul.x = pack2h(v.x - __half2float(hx), v.y - __half2float(hy));
    ul.y = pack2h(v.z - __half2float(hz), v.w - __half2float(hw));
    dhi[i] = uh;
    dlo[i] = ul;
}

// ---------------------------------------------------------------------------
// prep_all: x split + W1/W2 fp16 + bc1/bc2 + At1/At2 (single launch)
// ---------------------------------------------------------------------------
__global__ __launch_bounds__(256)
void prep_all_kernel(const float4* __restrict__ x, uint2* __restrict__ xhi, uint2* __restrict__ xlo,
                     const float4* __restrict__ W1, uint2* __restrict__ w1h,
                     const float4* __restrict__ W2, uint2* __restrict__ w2h,
                     const float* __restrict__ B1f, __half* __restrict__ bc1,
                     const float* __restrict__ B2f, __half* __restrict__ bc2,
                     const float* __restrict__ A1f, __half* __restrict__ at1,
                     const float* __restrict__ A2f, __half* __restrict__ at2) {
    const int stride = gridDim.x * blockDim.x;
    const int tid0 = blockIdx.x * blockDim.x + threadIdx.x;
    const int nx4 = M_TOT * D_DIM / 4;
    const int nw4 = H_DIM * D_DIM / 4;
    for (int i = tid0; i < nx4; i += stride) split_store4h(x[i], xhi, xlo, i);
    for (int i = tid0; i < nw4; i += stride) {
        float4 v = W1[i];
        uint2 u;
        u.x = pack2h(v.x, v.y);
        u.y = pack2h(v.z, v.w);
        w1h[i] = u;
    }
    for (int i = tid0; i < nw4; i += stride) {
        float4 v = W2[i];
        uint2 u;
        u.x = pack2h(v.x, v.y);
        u.y = pack2h(v.z, v.w);
        w2h[i] = u;
    }
    const __half hz = __float2half_rn(0.f);
    for (int n = tid0; n < H_DIM; n += stride) {
#pragma unroll
        for (int r = 0; r < 16; r++) {
            __half hi = __float2half_rn(B1f[n * 16 + r]);
            bc1[(size_t)n * 64 + r] = hi;
            bc1[(size_t)n * 64 + 16 + r] = hi;
            bc1[(size_t)n * 64 + 32 + r] = hz;
            bc1[(size_t)n * 64 + 48 + r] = hz;
        }
    }
    for (int n = tid0; n < D_DIM; n += stride) {
#pragma unroll
        for (int r = 0; r < 16; r++) {
            __half hi = __float2half_rn(B2f[n * 16 + r]);
            bc2[(size_t)n * 64 + r] = hi;
            bc2[(size_t)n * 64 + 16 + r] = hi;
            bc2[(size_t)n * 64 + 32 + r] = hz;
            bc2[(size_t)n * 64 + 48 + r] = hz;
        }
    }
    // A transposes: At[k][c] = A[c][k]
    for (int k = tid0; k < D_DIM; k += stride)
#pragma unroll
        for (int c = 0; c < 16; c++)
            at1[(size_t)k * 16 + c] = __float2half_rn(A1f[(size_t)c * D_DIM + k]);
    for (int k = tid0; k < H_DIM; k += stride)
#pragma unroll
        for (int c = 0; c < 16; c++)
            at2[(size_t)k * 16 + c] = __float2half_rn(A2f[(size_t)c * H_DIM + k]);
}

// ---------------------------------------------------------------------------
// proj kernels: t[row][0..15] = sum_k in[row][k] * At[k][0..15]
// block 128 = 32 rows x 4 K-splits; 16 fp32 accs/thread; shfl-reduce.
// In row once per row (not 16x); At via warp-uniform broadcast loads.
// ---------------------------------------------------------------------------
template <int IS_F32>
__global__ __launch_bounds__(128)
void proj_kernel(const void* __restrict__ In, const __half* __restrict__ At,
                 __half* __restrict__ Tc, int Kd) {
    const int tid = threadIdx.x;
    const int row = blockIdx.x * 32 + (tid >> 2);
    const int ks = tid & 3;
    const int kper = Kd >> 2;            // K-range per split
    const int k0 = ks * kper;

    float acc[16];
#pragma unroll
    for (int c = 0; c < 16; c++) acc[c] = 0.f;

    const int chunks = kper >> 3;        // 8 elems per chunk
    if (IS_F32) {
        const float4* xr = (const float4*)((const float*)In + (size_t)row * Kd + k0);
        for (int i = 0; i < chunks; i++) {
            float4 v0 = xr[i * 2 + 0], v1 = xr[i * 2 + 1];
            float hv[8] = {v0.x, v0.y, v0.z, v0.w, v1.x, v1.y, v1.z, v1.w};
#pragma unroll
            for (int j = 0; j < 8; j++) {
                const uint2* ap = (const uint2*)(At + (size_t)(k0 + i * 8 + j) * 16);
                uint2 a0 = ap[0], a1 = ap[1];
                float2 c0 = __half22float2(*(__half2*)&a0.x);
                float2 c1 = __half22float2(*(__half2*)&a0.y);
                float2 c2 = __half22float2(*(__half2*)&a1.x);
                float2 c3 = __half22float2(*(__half2*)&a1.y);
                // only 8 cols per uint2 pair? uint2 = 4 halves; need 16 -> 2 uint2x2
                const uint2* ap2 = ap + 2;
                uint2 b0 = ap2[0], b1 = ap2[1];
                float2 c4 = __half22float2(*(__half2*)&b0.x);
                float2 c5 = __half22float2(*(__half2*)&b0.y);
                float2 c6 = __half22float2(*(__half2*)&b1.x);
                float2 c7 = __half22float2(*(__half2*)&b1.y);
                float h = hv[j];
                acc[0] += h * c0.x; acc[1] += h * c0.y; acc[2] += h * c1.x; acc[3] += h * c1.y;
                acc[4] += h * c2.x; acc[5] += h * c2.y; acc[6] += h * c3.x; acc[7] += h * c3.y;
                acc[8] += h * c4.x; acc[9] += h * c4.y; acc[10] += h * c5.x; acc[11] += h * c5.y;
                acc[12] += h * c6.x; acc[13] += h * c6.y; acc[14] += h * c7.x; acc[15] += h * c7.y;
            }
        }
    } else {
        const uint4* hr = (const uint4*)((const __half*)In + (size_t)row * Kd + k0);
        for (int i = 0; i < chunks; i++) {
            uint4 u = hr[i];
            float2 p0 = __half22float2(*(__half2*)&u.x);
            float2 p1 = __half22float2(*(__half2*)&u.y);
            float2 p2 = __half22float2(*(__half2*)&u.z);
            float2 p3 = __half22float2(*(__half2*)&u.w);
            float hv[8] = {p0.x, p0.y, p1.x, p1.y, p2.x, p2.y, p3.x, p3.y};
#pragma unroll
            for (int j = 0; j < 8; j++) {
                const uint2* ap = (const uint2*)(At + (size_t)(k0 + i * 8 + j) * 16);
                uint2 a0 = ap[0], a1 = ap[1];
                const uint2* ap2 = ap + 2;
                uint2 b0 = ap2[0], b1 = ap2[1];
                float2 c0 = __half22float2(*(__half2*)&a0.x);
                float2 c1 = __half22float2(*(__half2*)&a0.y);
                float2 c2 = __half22float2(*(__half2*)&a1.x);
                float2 c3 = __half22float2(*(__half2*)&a1.y);
                float2 c4 = __half22float2(*(__half2*)&b0.x);
                float2 c5 = __half22float2(*(__half2*)&b0.y);
                float2 c6 = __half22float2(*(__half2*)&b1.x);
                float2 c7 = __half22float2(*(__half2*)&b1.y);
                float h = hv[j];
                acc[0] += h * c0.x; acc[1] += h * c0.y; acc[2] += h * c1.x; acc[3] += h * c1.y;
                acc[4] += h * c2.x; acc[5] += h * c2.y; acc[6] += h * c3.x; acc[7] += h * c3.y;
                acc[8] += h * c4.x; acc[9] += h * c4.y; acc[10] += h * c5.x; acc[11] += h * c5.y;
                acc[12] += h * c6.x; acc[13] += h * c6.y; acc[14] += h * c7.x; acc[15] += h * c7.y;
            }
        }
    }

    // reduce across the 4 K-split lanes (adjacent lanes)
#pragma unroll
    for (int c = 0; c < 16; c++) {
        acc[c] += __shfl_xor_sync(0xFFFFFFFF, acc[c], 1);
        acc[c] += __shfl_xor_sync(0xFFFFFFFF, acc[c], 2);
    }

    if (ks == 0) {
        uint4 w[4];
        uint32_t* wp = (uint32_t*)w;
#pragma unroll
        for (int p = 0; p < 8; p++) {
            float v0 = acc[p * 2], v1 = acc[p * 2 + 1];
            __half h0 = __float2half_rn(v0), h1 = __float2half_rn(v1);
            __half2 ph = __halves2half2(h0, h1);
            wp[p] = *(uint32_t*)&ph;                 // hi block (cols 0-15)
            wp[8 + p] = pack2h(v0 - __half2float(h0), v1 - __half2float(h1));  // lo block
        }
        uint4* dst = (uint4*)(Tc + (size_t)row * 64);
        dst[0] = w[0];
        dst[1] = w[1];
        dst[2] = w[2];
        dst[3] = w[3];
        dst[4] = make_uint4(0, 0, 0, 0);
        dst[5] = make_uint4(0, 0, 0, 0);
        dst[6] = make_uint4(0, 0, 0, 0);
        dst[7] = make_uint4(0, 0, 0, 0);
    }
}

// ---------------------------------------------------------------------------
// K-dim segments (2 split passes + LoRA tail), BK=64 chunks
// ---------------------------------------------------------------------------
struct Segs {
    const __half* a[3];
    const __half* b[3];
    int sa[3];
    int sb[3];
    int nchunks[3];
};

// ---------------------------------------------------------------------------
// fp16 mma.sync GEMM. CTA 128 x BNT, BK=64/iter, 256 threads, 8 warps
// (warp tile 32 x BNT/2), 2 CTAs/SM, 1 barrier per BK=64.
// ---------------------------------------------------------------------------
template <int DO_GELU, int BNT>
__global__ __launch_bounds__(256, 2)
void fc_mma_kernel(Segs segs, int total_chunks,
                   const float* __restrict__ bias,
                   __half* __restrict__ Chi, __half* __restrict__ Clo,
                   float* __restrict__ Cf, int Nld) {
    constexpr int NJ = BNT / 32;
    constexpr int A_BYTES = BM * ROWSTRIDE * 2;
    constexpr int B_BYTES = BNT * ROWSTRIDE * 2;
    constexpr int STG_BYTES = A_BYTES + B_BYTES;

    extern __shared__ char smem[];
    const uint32_t smem_base = smem_u32(smem);

    const int tid = threadIdx.x;
    const int wid = tid >> 5;
    const int lane = tid & 31;
    const int wm = wid >> 1;
    const int wn = wid & 1;
    const int m0 = blockIdx.y * BM;
    const int n0 = blockIdx.x * BNT;

    int ls = 0, lc = 0;

    const uint32_t aoff = ((uint32_t)(wm * 32 + (lane & 15)) * ROWSTRIDE + (lane >> 4) * 8) * 2;
    const uint32_t boff = ((uint32_t)(wn * (BNT / 2) + ((lane >> 4) & 1) * 8 + (lane & 7)) * ROWSTRIDE +
                           ((lane >> 3) & 1) * 8) * 2;

    float acc[2][NJ * 2][4];
#pragma unroll
    for (int i = 0; i < 2; i++)
#pragma unroll
        for (int j = 0; j < NJ * 2; j++)
#pragma unroll
            for (int k = 0; k < 4; k++) acc[i][j][k] = 0.f;

    auto load_tile = [&](int stage) {
        const __half* Ap = segs.a[ls];
        const __half* Bp = segs.b[ls];
        const int stA = segs.sa[ls];
        const int stB = segs.sb[ls];
        const int kk = lc * BK;
        const uint32_t sA = smem_base + stage * STG_BYTES;
        const uint32_t sB = sA + A_BYTES;
#pragma unroll
        for (int j = 0; j < 4; j++) {
            int u = j * 256 + tid;
            int row = u >> 3, grp = u & 7;
            int gm = m0 + row;
            if (gm >= M_TOT) gm = M_TOT - 1;
            CP_ASYNC16(sA + (uint32_t)(row * ROWSTRIDE + grp * 8) * 2,
                       Ap + (size_t)gm * stA + kk + grp * 8);
        }
#pragma unroll
        for (int j = 0; j < BNT / 32; j++) {
            int u = j * 256 + tid;
            int row = u >> 3, grp = u & 7;
            CP_ASYNC16(sB + (uint32_t)(row * ROWSTRIDE + grp * 8) * 2,
                       Bp + (size_t)(n0 + row) * stB + kk + grp * 8);
        }
        if (++lc == segs.nchunks[ls]) { lc = 0; ++ls; }
    };

#pragma unroll
    for (int s = 0; s < STAGES - 1; s++) {
        load_tile(s);
        CP_COMMIT();
    }

    for (int t = 0; t < total_chunks; t++) {
        CP_WAIT(STAGES - 2);
        __syncthreads();

        const uint32_t sA = smem_base + (t % STAGES) * STG_BYTES;
        const uint32_t sB = sA + A_BYTES;

#pragma unroll
        for (int sub = 0; sub < 2; sub++) {
            const uint32_t ksub = (uint32_t)(sub * 32) * 2;
            uint32_t af[2][2][4];
#pragma unroll
            for (int mi = 0; mi < 2; mi++)
#pragma unroll
                for (int k = 0; k < 2; k++)
                    LDSM4(af[mi][k], sA + aoff + ksub + (uint32_t)(mi * 16 * ROWSTRIDE + k * 16) * 2);

#pragma unroll
            for (int nj = 0; nj < NJ; nj++) {
                uint32_t bf[2][4];
#pragma unroll
                for (int k = 0; k < 2; k++)
                    LDSM4(bf[k], sB + boff + ksub + (uint32_t)(nj * 16 * ROWSTRIDE + k * 16) * 2);
#pragma unroll
                for (int mi = 0; mi < 2; mi++)
#pragma unroll
                    for (int h = 0; h < 2; h++) {
                        MMA16816H(acc[mi][nj * 2 + h], af[mi][0], bf[0][h * 2], bf[0][h * 2 + 1]);
                        MMA16816H(acc[mi][nj * 2 + h], af[mi][1], bf[1][h * 2], bf[1][h * 2 + 1]);
                    }
            }
        }

        if (t + STAGES - 1 < total_chunks) load_tile((t + STAGES - 1) % STAGES);
        CP_COMMIT();
    }

    // ---- epilogue ----
#pragma unroll
    for (int mi = 0; mi < 2; mi++) {
        const int rbase = m0 + wm * 32 + mi * 16 + (lane >> 2);
#pragma unroll
        for (int ni = 0; ni < NJ * 2; ni++) {
            const int gn = n0 + wn * (BNT / 2) + ni * 8 + (lane & 3) * 2;
            const float b0 = __ldg(bias + gn);
            const float b1 = __ldg(bias + gn + 1);
#pragma unroll
            for (int h = 0; h < 2; h++) {
                const int gm = rbase + h * 8;
                if (gm >= M_TOT) continue;
                float v0 = acc[mi][ni][h * 2 + 0] + b0;
                float v1 = acc[mi][ni][h * 2 + 1] + b1;
                if (DO_GELU) {
                    v0 = 0.5f * v0 * (1.0f + erff(v0 * 0.70710678118654752f));
                    v1 = 0.5f * v1 * (1.0f + erff(v1 * 0.70710678118654752f));
                    __half h0 = __float2half_rn(v0);
                    __half h1 = __float2half_rn(v1);
                    __half2 ph = __halves2half2(h0, h1);
                    *(uint32_t*)(Chi + (size_t)gm * Nld + gn) = *(uint32_t*)&ph;
                    *(uint32_t*)(Clo + (size_t)gm * Nld + gn) =
                        pack2h(v0 - __half2float(h0), v1 - __half2float(h1));
                } else {
                    *(float2*)(Cf + (size_t)gm * Nld + gn) = make_float2(v0, v1);
                }
            }
        }
    }
}

// ---------------------------------------------------------------------------
// Launch sequence
// ---------------------------------------------------------------------------
extern "C" void kernel_launch(void* const* d_in, const int* in_sizes, int n_in,
                              void* d_out, int out_size) {
    const float* x  = (const float*)d_in[0];
    const float* W1 = (const float*)d_in[1];
    const float* b1 = (const float*)d_in[2];
    const float* A1 = (const float*)d_in[3];
    const float* B1 = (const float*)d_in[4];
    const float* W2 = (const float*)d_in[5];
    const float* b2 = (const float*)d_in[6];
    const float* A2 = (const float*)d_in[7];
    const float* B2 = (const float*)d_in[8];
    float* out = (float*)d_out;

    __half *xhi, *xlo, *w1h, *w2h, *hhi, *hlo, *tc, *bc1, *bc2, *at1, *at2;
    cudaGetSymbolAddress((void**)&xhi, g_x_hi);
    cudaGetSymbolAddress((void**)&xlo, g_x_lo);
    cudaGetSymbolAddress((void**)&w1h, g_w1);
    cudaGetSymbolAddress((void**)&w2h, g_w2);
    cudaGetSymbolAddress((void**)&hhi, g_h_hi);
    cudaGetSymbolAddress((void**)&hlo, g_h_lo);
    cudaGetSymbolAddress((void**)&tc,  g_tc);
    cudaGetSymbolAddress((void**)&bc1, g_bc1);
    cudaGetSymbolAddress((void**)&bc2, g_bc2);
    cudaGetSymbolAddress((void**)&at1, g_at1);
    cudaGetSymbolAddress((void**)&at2, g_at2);

    constexpr int SM1 = STAGES * (BM * ROWSTRIDE * 2 + 128 * ROWSTRIDE * 2);
    constexpr int SM2 = STAGES * (BM * ROWSTRIDE * 2 + 64 * ROWSTRIDE * 2);
    cudaFuncSetAttribute((const void*)fc_mma_kernel<1, 128>,
                         cudaFuncAttributeMaxDynamicSharedMemorySize, SM1);
    cudaFuncSetAttribute((const void*)fc_mma_kernel<0, 64>,
                         cudaFuncAttributeMaxDynamicSharedMemorySize, SM2);

    prep_all_kernel<<<592, 256>>>(
        (const float4*)x, (uint2*)xhi, (uint2*)xlo,
        (const float4*)W1, (uint2*)w1h,
        (const float4*)W2, (uint2*)w2h,
        B1, bc1, B2, bc2, A1, at1, A2, at2);

    proj_kernel<1><<<M_TOT / 32, 128>>>((const void*)x, at1, tc, D_DIM);

    {
        Segs s;
        s.a[0] = xhi; s.b[0] = w1h; s.sa[0] = D_DIM; s.sb[0] = D_DIM; s.nchunks[0] = D_DIM / BK;
        s.a[1] = xlo; s.b[1] = w1h; s.sa[1] = D_DIM; s.sb[1] = D_DIM; s.nchunks[1] = D_DIM / BK;
        s.a[2] = tc;  s.b[2] = bc1; s.sa[2] = 64;    s.sb[2] = 64;    s.nchunks[2] = 1;
        int total = 2 * (D_DIM / BK) + 1;  // 25
        dim3 grid(H_DIM / 128, (M_TOT + BM - 1) / BM);
        fc_mma_kernel<1, 128><<<grid, 256, SM1>>>(s, total, b1, hhi, hlo, nullptr, H_DIM);
    }

    proj_kernel<0><<<M_TOT / 32, 128>>>((const void*)hhi, at2, tc, H_DIM);

    {
        Segs s;
        s.a[0] = hhi; s.b[0] = w2h; s.sa[0] = H_DIM; s.sb[0] = H_DIM; s.nchunks[0] = H_DIM / BK;
        s.a[1] = hlo; s.b[1] = w2h; s.sa[1] = H_DIM; s.sb[1] = H_DIM; s.nchunks[1] = H_DIM / BK;
        s.a[2] = tc;  s.b[2] = bc2; s.sa[2] = 64;    s.sb[2] = 64;    s.nchunks[2] = 1;
        int total = 2 * (H_DIM / BK) + 1;  // 97
        dim3 grid(D_DIM / 64, (M_TOT + BM - 1) / BM);
        fc_mma_kernel<0, 64><<<grid, 256, SM2>>>(s, total, b2, nullptr, nullptr, out, D_DIM);
    }
}